// round 9
// baseline (speedup 1.0000x reference)
#include <cuda_runtime.h>
#include <cuda_fp16.h>
#include <cstdint>
#include <math.h>

#define D       128
#define NMAX    8192
#define TAU_INV 10.0f
#define EX2K    14.4269504088896f   // TAU_INV * log2(e)
#define TM      128
#define NTT     64                  // tiles per dimension
#define NTILES_TRI (NTT * (NTT + 1) / 2)   // 2080
#define GMAIN   296                 // 2 CTAs per SM, persistent

// scratch (device globals; no allocation allowed). Statics start zeroed;
// the finisher CTA restores g_cls/g_cnt/g_ticket to zero each run.
__device__ __half g_ph[NMAX * D];      // normalized rows, f16
__device__ float  g_S[NMAX];           // exp-sum accumulators (zeroed by prep)
__device__ float  g_cls[2][D];         // per-class vector sums
__device__ int    g_cnt[2];
__device__ unsigned int g_ticket;

// ---------------------------------------------------------------------------
__device__ __forceinline__ uint32_t smem_u32(const void* p) {
    uint32_t a;
    asm("{ .reg .u64 t; cvta.to.shared.u64 t, %1; cvt.u32.u64 %0, t; }"
        : "=r"(a) : "l"(p));
    return a;
}
__device__ __forceinline__ void ldsm4(uint32_t r[4], uint32_t addr) {
    asm volatile("ldmatrix.sync.aligned.m8n8.x4.shared.b16 {%0,%1,%2,%3}, [%4];"
                 : "=r"(r[0]), "=r"(r[1]), "=r"(r[2]), "=r"(r[3]) : "r"(addr));
}
__device__ __forceinline__ void mma16816(float c[4], const uint32_t a[4],
                                         const uint32_t b[2]) {
    asm volatile(
        "mma.sync.aligned.m16n8k16.row.col.f32.f16.f16.f32 "
        "{%0,%1,%2,%3}, {%4,%5,%6,%7}, {%8,%9}, {%0,%1,%2,%3};"
        : "+f"(c[0]), "+f"(c[1]), "+f"(c[2]), "+f"(c[3])
        : "r"(a[0]), "r"(a[1]), "r"(a[2]), "r"(a[3]), "r"(b[0]), "r"(b[1]));
}
__device__ __forceinline__ void cp16(uint32_t saddr, const void* g) {
    asm volatile("cp.async.cg.shared.global [%0], [%1], 16;"
                 :: "r"(saddr), "l"(g) : "memory");
}
__device__ __forceinline__ float ex2(float x) {
    float r;
    asm("ex2.approx.f32 %0, %1;" : "=f"(r) : "f"(x));
    return r;
}
#define CP_COMMIT() asm volatile("cp.async.commit_group;" ::: "memory")
#define CP_WAIT(n)  asm volatile("cp.async.wait_group %0;" :: "n"(n) : "memory")

#define A_OFF  0u
#define B0_OFF 32768u
#define B1_OFF 65536u
#define SMEM_TOTAL 98304

// ---------------------------------------------------------------------------
// Kernel 1: normalize rows -> f16 table; class sums; zero g_S.
// ---------------------------------------------------------------------------
__global__ void prep_kernel(const float* __restrict__ zi,
                            const float* __restrict__ zj,
                            const int*   __restrict__ y, int B) {
    __shared__ float cls_s[2][D];
    __shared__ int   cnt_s[2];
    int warp = threadIdx.x >> 5, lane = threadIdx.x & 31;
    int t = threadIdx.x;
    if (t < 2 * D) ((float*)cls_s)[t] = 0.f;
    if (t < 2) cnt_s[t] = 0;
    __syncthreads();

    int row  = blockIdx.x * 8 + warp;
    const float* src = (row < B) ? (zi + (size_t)row * D)
                                 : (zj + (size_t)(row - B) * D);
    float4 v = ((const float4*)src)[lane];
    float ss = v.x * v.x + v.y * v.y + v.z * v.z + v.w * v.w;
    #pragma unroll
    for (int o = 16; o > 0; o >>= 1) ss += __shfl_xor_sync(0xffffffffu, ss, o);
    float s = 1.f / fmaxf(sqrtf(ss), 1e-8f);
    float4 pn = make_float4(v.x * s, v.y * s, v.z * s, v.w * s);

    __half2 h0 = __floats2half2_rn(pn.x, pn.y);
    __half2 h1 = __floats2half2_rn(pn.z, pn.w);
    uint2 u;
    u.x = *reinterpret_cast<unsigned int*>(&h0);
    u.y = *reinterpret_cast<unsigned int*>(&h1);
    ((uint2*)(g_ph + (size_t)row * D))[lane] = u;

    int lbl = y[(row < B) ? row : (row - B)];
    if (lane == 0) {
        g_S[row] = 0.f;
        atomicAdd(&cnt_s[lbl], 1);
    }
    atomicAdd(&cls_s[lbl][lane * 4 + 0], pn.x);
    atomicAdd(&cls_s[lbl][lane * 4 + 1], pn.y);
    atomicAdd(&cls_s[lbl][lane * 4 + 2], pn.z);
    atomicAdd(&cls_s[lbl][lane * 4 + 3], pn.w);
    __syncthreads();
    if (t < 2 * D) atomicAdd(&((float*)g_cls)[t], ((float*)cls_s)[t]);
    if (t < 2)     atomicAdd(&g_cnt[t], cnt_s[t]);
}

// ---------------------------------------------------------------------------
__device__ __forceinline__ void load_tile(uint32_t dst, int base, int tid) {
    for (int u = tid; u < TM * 16; u += 256) {
        int rr = u >> 4, cc = u & 15;
        cp16(dst + (uint32_t)rr * 256u + (uint32_t)((cc ^ (rr & 7)) << 4),
             g_ph + (size_t)(base + rr) * D + cc * 8);
    }
}

// ---------------------------------------------------------------------------
// Kernel 2: persistent symmetric HMMA + last-CTA fused finalize.
// ---------------------------------------------------------------------------
__global__ __launch_bounds__(256, 2)
void main_kernel(float* __restrict__ out) {
    extern __shared__ char sm[];
    __shared__ bool is_last;
    const uint32_t smb = smem_u32(sm);

    const int tid = threadIdx.x, lane = tid & 31, wid = tid >> 5;
    const int warp_m = wid >> 2, warp_n = wid & 3;

    const int lo = (int)(((long long)blockIdx.x * NTILES_TRI) / GMAIN);
    const int hi = (int)(((long long)(blockIdx.x + 1) * NTILES_TRI) / GMAIN);

    // decode starting (r, c)
    int r = 0;
    while ((r + 1) * (2 * NTT - r) / 2 <= lo) r++;
    int c = r + (lo - r * (2 * NTT - r + 1) / 2);

    load_tile(smb + A_OFF, r * TM, tid);
    load_tile(smb + B0_OFF, c * TM, tid);
    CP_COMMIT();

    // ldsm address precompute
    const int g = lane >> 3;
    uint32_t a_off[4], a_msk[4];
    #pragma unroll
    for (int mt = 0; mt < 4; mt++) {
        int row = warp_m * 64 + mt * 16 + (g & 1) * 8 + (lane & 7);
        a_off[mt] = smb + A_OFF + (uint32_t)row * 256u;
        a_msk[mt] = (uint32_t)(row & 7);
    }
    const int a_cadd = g >> 1;
    uint32_t b_row[2], b_msk[2];
    #pragma unroll
    for (int nt2 = 0; nt2 < 2; nt2++) {
        int row = warp_n * 32 + nt2 * 16 + (g >> 1) * 8 + (lane & 7);
        b_row[nt2] = (uint32_t)row * 256u;
        b_msk[nt2] = (uint32_t)(row & 7);
    }
    const int b_cadd = g & 1;

    float es[8];
    #pragma unroll
    for (int s = 0; s < 8; s++) es[s] = 0.f;
    int parity = 0;
    int accr = r;                 // row panel owning the es[] accumulations

    for (int t = lo; t < hi; t++) {
        const int tr = r, tc = c;
        const bool isdiag = (tr == tc);
        int nr = r, nc = c + 1;
        if (nc == NTT) { nr = r + 1; nc = nr; }
        const bool havenext = (t + 1 < hi);

        __syncthreads();
        if (havenext) {
            load_tile(smb + (parity ? B0_OFF : B1_OFF), nc * TM, tid);
            CP_COMMIT();
            CP_WAIT(1);
        } else {
            CP_WAIT(0);
        }
        __syncthreads();

        // ---- GEMM ----------------------------------------------------------
        const uint32_t bbase = smb + (parity ? B1_OFF : B0_OFF);
        float acc[4][4][4];
        #pragma unroll
        for (int mt = 0; mt < 4; mt++)
            #pragma unroll
            for (int nt = 0; nt < 4; nt++)
                #pragma unroll
                for (int k = 0; k < 4; k++) acc[mt][nt][k] = 0.f;

        #pragma unroll
        for (int ks = 0; ks < 8; ks++) {
            uint32_t af[4][4], bf[2][4];
            #pragma unroll
            for (int mt = 0; mt < 4; mt++)
                ldsm4(af[mt], a_off[mt] +
                      (uint32_t)(((2 * ks + a_cadd) ^ a_msk[mt]) << 4));
            #pragma unroll
            for (int nt2 = 0; nt2 < 2; nt2++)
                ldsm4(bf[nt2], bbase + b_row[nt2] +
                      (uint32_t)(((2 * ks + b_cadd) ^ b_msk[nt2]) << 4));
            #pragma unroll
            for (int mt = 0; mt < 4; mt++)
                #pragma unroll
                for (int nt = 0; nt < 4; nt++)
                    mma16816(acc[mt][nt], af[mt], &bf[nt >> 1][(nt & 1) * 2]);
        }

        // ---- epilogue ---------------------------------------------------------
        float csl[8];
        #pragma unroll
        for (int s = 0; s < 8; s++) csl[s] = 0.f;
        #pragma unroll
        for (int nt = 0; nt < 4; nt++) {
            #pragma unroll
            for (int mt = 0; mt < 4; mt++) {
                #pragma unroll
                for (int q = 0; q < 4; q++) {
                    float e = ex2(acc[mt][nt][q] * EX2K);
                    if (isdiag) {
                        int jl = warp_n * 32 + nt * 8 + (lane & 3) * 2 + (q & 1);
                        int il = warp_m * 64 + mt * 16 + (lane >> 2) + ((q < 2) ? 0 : 8);
                        if (jl == il) e = 0.f;
                    }
                    es[mt * 2 + (q >> 1)] += e;
                    csl[nt * 2 + (q & 1)] += e;
                }
            }
        }
        // column sums -> global atomics (skip for diag: row path covers it)
        if (!isdiag) {
            int colBase = tc * TM;
            #pragma unroll
            for (int s = 0; s < 8; s++) {
                float v = csl[s];
                v += __shfl_xor_sync(0xffffffffu, v, 4);
                v += __shfl_xor_sync(0xffffffffu, v, 8);
                v += __shfl_xor_sync(0xffffffffu, v, 16);
                if (lane < 4)
                    atomicAdd(&g_S[colBase + warp_n * 32 + (s >> 1) * 8 + lane * 2 + (s & 1)], v);
            }
        }

        // ---- row-panel change while continuing: flush es, reload A ------------
        if (havenext && nr != tr) {
            int rowBase = accr * TM;
            #pragma unroll
            for (int s = 0; s < 8; s++) {
                float e = es[s];
                e += __shfl_xor_sync(0xffffffffu, e, 1);
                e += __shfl_xor_sync(0xffffffffu, e, 2);
                if ((lane & 3) == 0)
                    atomicAdd(&g_S[rowBase + warp_m * 64 + (s >> 1) * 16 +
                                   (lane >> 2) + (s & 1) * 8], e);
                es[s] = 0.f;
            }
            accr = nr;
            __syncthreads();   // all warps done reading A
            load_tile(smb + A_OFF, nr * TM, tid);
            CP_COMMIT();
        }
        r = nr; c = nc; parity ^= 1;
    }

    // final row flush — accr owns the es[] accumulations
    {
        int rowBase = accr * TM;
        #pragma unroll
        for (int s = 0; s < 8; s++) {
            float e = es[s];
            e += __shfl_xor_sync(0xffffffffu, e, 1);
            e += __shfl_xor_sync(0xffffffffu, e, 2);
            if ((lane & 3) == 0)
                atomicAdd(&g_S[rowBase + warp_m * 64 + (s >> 1) * 16 +
                               (lane >> 2) + (s & 1) * 8], e);
        }
    }

    // ---- last-CTA fused finalize --------------------------------------------
    __threadfence();
    __syncthreads();
    if (tid == 0)
        is_last = (atomicAdd(&g_ticket, 1u) == GMAIN - 1u);
    __syncthreads();
    if (!is_last) return;
    __threadfence();   // acquire all g_S / g_cls / g_cnt writes

    __shared__ float ws[8];
    float local = 0.f;
    for (int i = tid; i < NMAX; i += 256) local += __logf(g_S[i]);
    #pragma unroll
    for (int o = 16; o > 0; o >>= 1) local += __shfl_xor_sync(0xffffffffu, local, o);
    if (lane == 0) ws[wid] = local;
    __syncthreads();
    if (wid < 2) {
        // class term: warps 0 and 1, one class each
        float4 cv = ((const float4*)(g_cls[wid]))[lane];
        float nsq = cv.x * cv.x + cv.y * cv.y + cv.z * cv.z + cv.w * cv.w;
        #pragma unroll
        for (int o = 16; o > 0; o >>= 1) nsq += __shfl_xor_sync(0xffffffffu, nsq, o);
        if (lane == 0) {
            float cnt = (float)g_cnt[wid];
            ws[wid] -= TAU_INV * (nsq - cnt) / (cnt - 1.f);
        }
    }
    __syncthreads();
    if (tid == 0) {
        float tot = ws[0] + ws[1] + ws[2] + ws[3] + ws[4] + ws[5] + ws[6] + ws[7];
        out[0] = tot;
        // restore invariants for the next graph replay
        g_ticket = 0u;
        g_cnt[0] = 0; g_cnt[1] = 0;
    }
    // zero g_cls for next run
    if (tid < 2 * D) ((float*)g_cls)[tid] = 0.f;
}

// ---------------------------------------------------------------------------
extern "C" void kernel_launch(void* const* d_in, const int* in_sizes, int n_in,
                              void* d_out, int out_size) {
    const float* zi = (const float*)d_in[0];
    const float* zj = (const float*)d_in[1];
    const int*   y  = (const int*)d_in[2];
    int B = in_sizes[2];
    int N = 2 * B;

    prep_kernel<<<N / 8, 256>>>(zi, zj, y, B);

    cudaFuncSetAttribute(main_kernel, cudaFuncAttributeMaxDynamicSharedMemorySize,
                         SMEM_TOTAL);
    main_kernel<<<GMAIN, 256, SMEM_TOTAL>>>((float*)d_out);
}

// round 10
// speedup vs baseline: 1.1355x; 1.1355x over previous
#include <cuda_runtime.h>
#include <cuda_fp16.h>
#include <cstdint>
#include <math.h>

#define D       128
#define NMAX    8192
#define TAU_INV 10.0f
#define EX2K    14.4269504088896f   // TAU_INV * log2(e)
#define TM      128
#define NTT     64                  // tiles per dimension
#define NTILES_TRI (NTT * (NTT + 1) / 2)   // 2080
#define GMAIN   296                 // 2 CTAs per SM, persistent

// scratch (device globals; no allocation allowed). g_cls/g_cnt are restored
// to zero by finalize after use, so every graph replay sees them zeroed.
__device__ __half g_ph[NMAX * D];      // normalized rows, f16 (B operand)
__device__ __half g_phA[NMAX * D];     // normalized rows * EX2K, f16 (A operand)
__device__ float  g_S[NMAX];           // exp-sum accumulators (zeroed by prep)
__device__ float  g_cls[2][D];         // per-class vector sums
__device__ int    g_cnt[2];

// ---------------------------------------------------------------------------
__device__ __forceinline__ uint32_t smem_u32(const void* p) {
    uint32_t a;
    asm("{ .reg .u64 t; cvta.to.shared.u64 t, %1; cvt.u32.u64 %0, t; }"
        : "=r"(a) : "l"(p));
    return a;
}
__device__ __forceinline__ void ldsm4(uint32_t r[4], uint32_t addr) {
    asm volatile("ldmatrix.sync.aligned.m8n8.x4.shared.b16 {%0,%1,%2,%3}, [%4];"
                 : "=r"(r[0]), "=r"(r[1]), "=r"(r[2]), "=r"(r[3]) : "r"(addr));
}
// NOTE: non-volatile — lets ptxas schedule MMAs between/around the LDSMs.
__device__ __forceinline__ void mma16816(float c[4], const uint32_t a[4],
                                         const uint32_t b[2]) {
    asm("mma.sync.aligned.m16n8k16.row.col.f32.f16.f16.f32 "
        "{%0,%1,%2,%3}, {%4,%5,%6,%7}, {%8,%9}, {%0,%1,%2,%3};"
        : "+f"(c[0]), "+f"(c[1]), "+f"(c[2]), "+f"(c[3])
        : "r"(a[0]), "r"(a[1]), "r"(a[2]), "r"(a[3]), "r"(b[0]), "r"(b[1]));
}
__device__ __forceinline__ void cp16(uint32_t saddr, const void* g) {
    asm volatile("cp.async.cg.shared.global [%0], [%1], 16;"
                 :: "r"(saddr), "l"(g) : "memory");
}
__device__ __forceinline__ float ex2(float x) {
    float r;
    asm("ex2.approx.f32 %0, %1;" : "=f"(r) : "f"(x));
    return r;
}
#define CP_COMMIT() asm volatile("cp.async.commit_group;" ::: "memory")
#define CP_WAIT(n)  asm volatile("cp.async.wait_group %0;" :: "n"(n) : "memory")

#define A_OFF  0u
#define B0_OFF 32768u
#define B1_OFF 65536u
#define SMEM_TOTAL 98304

// ---------------------------------------------------------------------------
// Kernel 1: normalize rows -> f16 tables (plain + EX2K-scaled); class sums;
// zero g_S; block 0 zeroes out[0].
// ---------------------------------------------------------------------------
__global__ void prep_kernel(const float* __restrict__ zi,
                            const float* __restrict__ zj,
                            const int*   __restrict__ y, int B,
                            float* __restrict__ out) {
    __shared__ float cls_s[2][D];
    __shared__ int   cnt_s[2];
    int warp = threadIdx.x >> 5, lane = threadIdx.x & 31;
    int t = threadIdx.x;
    if (t < 2 * D) ((float*)cls_s)[t] = 0.f;
    if (t < 2) cnt_s[t] = 0;
    if (blockIdx.x == 0 && t == 0) out[0] = 0.f;
    __syncthreads();

    int row  = blockIdx.x * 8 + warp;
    const float* src = (row < B) ? (zi + (size_t)row * D)
                                 : (zj + (size_t)(row - B) * D);
    float4 v = ((const float4*)src)[lane];
    float ss = v.x * v.x + v.y * v.y + v.z * v.z + v.w * v.w;
    #pragma unroll
    for (int o = 16; o > 0; o >>= 1) ss += __shfl_xor_sync(0xffffffffu, ss, o);
    float s = 1.f / fmaxf(sqrtf(ss), 1e-8f);
    float4 pn = make_float4(v.x * s, v.y * s, v.z * s, v.w * s);

    __half2 h0 = __floats2half2_rn(pn.x, pn.y);
    __half2 h1 = __floats2half2_rn(pn.z, pn.w);
    uint2 u;
    u.x = *reinterpret_cast<unsigned int*>(&h0);
    u.y = *reinterpret_cast<unsigned int*>(&h1);
    ((uint2*)(g_ph + (size_t)row * D))[lane] = u;

    __half2 a0 = __floats2half2_rn(pn.x * EX2K, pn.y * EX2K);
    __half2 a1 = __floats2half2_rn(pn.z * EX2K, pn.w * EX2K);
    uint2 ua;
    ua.x = *reinterpret_cast<unsigned int*>(&a0);
    ua.y = *reinterpret_cast<unsigned int*>(&a1);
    ((uint2*)(g_phA + (size_t)row * D))[lane] = ua;

    int lbl = y[(row < B) ? row : (row - B)];
    if (lane == 0) {
        g_S[row] = 0.f;
        atomicAdd(&cnt_s[lbl], 1);
    }
    atomicAdd(&cls_s[lbl][lane * 4 + 0], pn.x);
    atomicAdd(&cls_s[lbl][lane * 4 + 1], pn.y);
    atomicAdd(&cls_s[lbl][lane * 4 + 2], pn.z);
    atomicAdd(&cls_s[lbl][lane * 4 + 3], pn.w);
    __syncthreads();
    if (t < 2 * D) atomicAdd(&((float*)g_cls)[t], ((float*)cls_s)[t]);
    if (t < 2)     atomicAdd(&g_cnt[t], cnt_s[t]);
}

// ---------------------------------------------------------------------------
__device__ __forceinline__ void load_tile(uint32_t dst, const __half* table,
                                          int base, int tid) {
    for (int u = tid; u < TM * 16; u += 256) {
        int rr = u >> 4, cc = u & 15;
        cp16(dst + (uint32_t)rr * 256u + (uint32_t)((cc ^ (rr & 7)) << 4),
             table + (size_t)(base + rr) * D + cc * 8);
    }
}

// ---------------------------------------------------------------------------
// Kernel 2: persistent symmetric HMMA, software-pipelined K loop.
// 296 CTAs, contiguous triangular chunks; A-panel (scaled table) reused,
// B double-buffered. acc = EX2K * dot -> epilogue is ex2 + adds only.
// ---------------------------------------------------------------------------
__global__ __launch_bounds__(256, 2)
void main_kernel() {
    extern __shared__ char sm[];
    const uint32_t smb = smem_u32(sm);

    const int tid = threadIdx.x, lane = tid & 31, wid = tid >> 5;
    const int warp_m = wid >> 2, warp_n = wid & 3;

    const int lo = (int)(((long long)blockIdx.x * NTILES_TRI) / GMAIN);
    const int hi = (int)(((long long)(blockIdx.x + 1) * NTILES_TRI) / GMAIN);

    int r = 0;
    while ((r + 1) * (2 * NTT - r) / 2 <= lo) r++;
    int c = r + (lo - r * (2 * NTT - r + 1) / 2);

    load_tile(smb + A_OFF, g_phA, r * TM, tid);
    load_tile(smb + B0_OFF, g_ph, c * TM, tid);
    CP_COMMIT();

    // ldsm address precompute
    const int g = lane >> 3;
    uint32_t a_off[4], a_msk[4];
    #pragma unroll
    for (int mt = 0; mt < 4; mt++) {
        int row = warp_m * 64 + mt * 16 + (g & 1) * 8 + (lane & 7);
        a_off[mt] = smb + A_OFF + (uint32_t)row * 256u;
        a_msk[mt] = (uint32_t)(row & 7);
    }
    const int a_cadd = g >> 1;
    uint32_t b_row[2], b_msk[2];
    #pragma unroll
    for (int nt2 = 0; nt2 < 2; nt2++) {
        int row = warp_n * 32 + nt2 * 16 + (g >> 1) * 8 + (lane & 7);
        b_row[nt2] = (uint32_t)row * 256u;
        b_msk[nt2] = (uint32_t)(row & 7);
    }
    const int b_cadd = g & 1;

#define AADDR(mt, ks) (a_off[mt] + (uint32_t)(((2 * (ks) + a_cadd) ^ a_msk[mt]) << 4))
#define BADDR(n2, ks) (bbase + b_row[n2] + (uint32_t)(((2 * (ks) + b_cadd) ^ b_msk[n2]) << 4))

    float es[8];
    #pragma unroll
    for (int s = 0; s < 8; s++) es[s] = 0.f;
    int parity = 0;
    int accr = r;                 // row panel owning the es[] accumulations

    for (int t = lo; t < hi; t++) {
        const int tr = r, tc = c;
        const bool isdiag = (tr == tc);
        int nr = r, nc = c + 1;
        if (nc == NTT) { nr = r + 1; nc = nr; }
        const bool havenext = (t + 1 < hi);

        __syncthreads();
        if (havenext) {
            load_tile(smb + (parity ? B0_OFF : B1_OFF), g_ph, nc * TM, tid);
            CP_COMMIT();
            CP_WAIT(1);
        } else {
            CP_WAIT(0);
        }
        __syncthreads();

        // ---- GEMM: software-pipelined over ks (B) and mt (A) -----------------
        const uint32_t bbase = smb + (parity ? B1_OFF : B0_OFF);
        float acc[4][4][4];
        #pragma unroll
        for (int mt = 0; mt < 4; mt++)
            #pragma unroll
            for (int nt = 0; nt < 4; nt++)
                #pragma unroll
                for (int k = 0; k < 4; k++) acc[mt][nt][k] = 0.f;

        uint32_t afb[2][4], bfb[2][2][4];
        ldsm4(bfb[0][0], BADDR(0, 0));
        ldsm4(bfb[0][1], BADDR(1, 0));
        ldsm4(afb[0], AADDR(0, 0));
        #pragma unroll
        for (int ks = 0; ks < 8; ks++) {
            const int kb = ks & 1;
            if (ks < 7) {
                ldsm4(bfb[kb ^ 1][0], BADDR(0, ks + 1));
                ldsm4(bfb[kb ^ 1][1], BADDR(1, ks + 1));
            }
            #pragma unroll
            for (int mt = 0; mt < 4; mt++) {
                const int ab = mt & 1;
                if (mt < 3)      ldsm4(afb[ab ^ 1], AADDR(mt + 1, ks));
                else if (ks < 7) ldsm4(afb[ab ^ 1], AADDR(0, ks + 1));
                #pragma unroll
                for (int nt = 0; nt < 4; nt++)
                    mma16816(acc[mt][nt], afb[ab], &bfb[kb][nt >> 1][(nt & 1) * 2]);
            }
        }

        // ---- epilogue: ex2 + row/col accumulation ----------------------------
        float csl[8];
        #pragma unroll
        for (int s = 0; s < 8; s++) csl[s] = 0.f;
        #pragma unroll
        for (int nt = 0; nt < 4; nt++) {
            #pragma unroll
            for (int mt = 0; mt < 4; mt++) {
                #pragma unroll
                for (int q = 0; q < 4; q++) {
                    float e = ex2(acc[mt][nt][q]);
                    if (isdiag) {
                        int jl = warp_n * 32 + nt * 8 + (lane & 3) * 2 + (q & 1);
                        int il = warp_m * 64 + mt * 16 + (lane >> 2) + ((q < 2) ? 0 : 8);
                        if (jl == il) e = 0.f;
                    }
                    es[mt * 2 + (q >> 1)] += e;
                    csl[nt * 2 + (q & 1)] += e;
                }
            }
        }
        if (!isdiag) {
            int colBase = tc * TM;
            #pragma unroll
            for (int s = 0; s < 8; s++) {
                float v = csl[s];
                v += __shfl_xor_sync(0xffffffffu, v, 4);
                v += __shfl_xor_sync(0xffffffffu, v, 8);
                v += __shfl_xor_sync(0xffffffffu, v, 16);
                if (lane < 4)
                    atomicAdd(&g_S[colBase + warp_n * 32 + (s >> 1) * 8 + lane * 2 + (s & 1)], v);
            }
        }

        // ---- row-panel change while continuing: flush es, reload A ------------
        if (havenext && nr != tr) {
            int rowBase = accr * TM;
            #pragma unroll
            for (int s = 0; s < 8; s++) {
                float e = es[s];
                e += __shfl_xor_sync(0xffffffffu, e, 1);
                e += __shfl_xor_sync(0xffffffffu, e, 2);
                if ((lane & 3) == 0)
                    atomicAdd(&g_S[rowBase + warp_m * 64 + (s >> 1) * 16 +
                                   (lane >> 2) + (s & 1) * 8], e);
                es[s] = 0.f;
            }
            accr = nr;
            __syncthreads();   // all warps done reading A
            load_tile(smb + A_OFF, g_phA, nr * TM, tid);
            CP_COMMIT();
        }
        r = nr; c = nc; parity ^= 1;
    }

    // final row flush — accr owns the es[] accumulations
    {
        int rowBase = accr * TM;
        #pragma unroll
        for (int s = 0; s < 8; s++) {
            float e = es[s];
            e += __shfl_xor_sync(0xffffffffu, e, 1);
            e += __shfl_xor_sync(0xffffffffu, e, 2);
            if ((lane & 3) == 0)
                atomicAdd(&g_S[rowBase + warp_m * 64 + (s >> 1) * 16 +
                               (lane >> 2) + (s & 1) * 8], e);
        }
    }
#undef AADDR
#undef BADDR
}

// ---------------------------------------------------------------------------
// Kernel 3: loss = sum_i log S_i - tau_inv * sum_c (||S_c||^2 - cnt_c)/(cnt_c-1)
// Block 0 also restores g_cls/g_cnt to zero for the next graph replay.
// ---------------------------------------------------------------------------
__global__ void finalize_kernel(float* __restrict__ out) {
    __shared__ float ws[8];
    int t = threadIdx.x, lane = t & 31, warp = t >> 5;
    int row = blockIdx.x * 256 + t;
    float local = logf(g_S[row]);
    #pragma unroll
    for (int o = 16; o > 0; o >>= 1) local += __shfl_xor_sync(0xffffffffu, local, o);
    if (lane == 0) ws[warp] = local;
    __syncthreads();
    if (t < 8) {
        float v = ws[t];
        #pragma unroll
        for (int o = 4; o > 0; o >>= 1) v += __shfl_xor_sync(0x000000ffu, v, o);
        if (t == 0) atomicAdd(out, v);
    }
    if (blockIdx.x == 0) {
        if (warp < 2) {
            float4 cv = ((const float4*)(g_cls[warp]))[lane];
            float nsq = cv.x * cv.x + cv.y * cv.y + cv.z * cv.z + cv.w * cv.w;
            #pragma unroll
            for (int o = 16; o > 0; o >>= 1) nsq += __shfl_xor_sync(0xffffffffu, nsq, o);
            if (lane == 0) {
                float cnt = (float)g_cnt[warp];
                atomicAdd(out, -TAU_INV * (nsq - cnt) / (cnt - 1.f));
            }
        }
        __syncthreads();
        if (t < 2 * D) ((float*)g_cls)[t] = 0.f;
        if (t < 2) g_cnt[t] = 0;
    }
}

// ---------------------------------------------------------------------------
extern "C" void kernel_launch(void* const* d_in, const int* in_sizes, int n_in,
                              void* d_out, int out_size) {
    const float* zi = (const float*)d_in[0];
    const float* zj = (const float*)d_in[1];
    const int*   y  = (const int*)d_in[2];
    int B = in_sizes[2];
    int N = 2 * B;

    prep_kernel<<<N / 8, 256>>>(zi, zj, y, B, (float*)d_out);

    cudaFuncSetAttribute(main_kernel, cudaFuncAttributeMaxDynamicSharedMemorySize,
                         SMEM_TOTAL);
    main_kernel<<<GMAIN, 256, SMEM_TOTAL>>>();

    finalize_kernel<<<N / 256, 256>>>((float*)d_out);
}

// round 11
// speedup vs baseline: 1.2990x; 1.1439x over previous
#include <cuda_runtime.h>
#include <cuda_fp16.h>
#include <cstdint>
#include <math.h>

#define D       128
#define NMAX    8192
#define TAU_INV 10.0f
#define EX2K    14.4269504088896f   // TAU_INV * log2(e)
#define TM      128
#define NTT     64                  // tiles per dimension
#define NTILES_TRI (NTT * (NTT + 1) / 2)   // 2080
#define GMAIN   296                 // 2 CTAs per SM, persistent

// scratch (device globals; no allocation allowed). g_cls/g_cnt are restored
// to zero by finalize after use, so every graph replay sees them zeroed.
__device__ __half g_ph[NMAX * D];      // normalized rows, f16 (B operand)
__device__ __half g_phA[NMAX * D];     // normalized rows * EX2K, f16 (A operand)
__device__ float  g_S[NMAX];           // exp-sum accumulators (zeroed by prep)
__device__ float  g_cls[2][D];         // per-class vector sums
__device__ int    g_cnt[2];

// ---------------------------------------------------------------------------
__device__ __forceinline__ uint32_t smem_u32(const void* p) {
    uint32_t a;
    asm("{ .reg .u64 t; cvta.to.shared.u64 t, %1; cvt.u32.u64 %0, t; }"
        : "=r"(a) : "l"(p));
    return a;
}
__device__ __forceinline__ void ldsm4(uint32_t r[4], uint32_t addr) {
    asm volatile("ldmatrix.sync.aligned.m8n8.x4.shared.b16 {%0,%1,%2,%3}, [%4];"
                 : "=r"(r[0]), "=r"(r[1]), "=r"(r[2]), "=r"(r[3]) : "r"(addr));
}
// NOTE: non-volatile — lets ptxas schedule MMAs between/around the LDSMs.
__device__ __forceinline__ void mma16816(float c[4], const uint32_t a[4],
                                         const uint32_t b[2]) {
    asm("mma.sync.aligned.m16n8k16.row.col.f32.f16.f16.f32 "
        "{%0,%1,%2,%3}, {%4,%5,%6,%7}, {%8,%9}, {%0,%1,%2,%3};"
        : "+f"(c[0]), "+f"(c[1]), "+f"(c[2]), "+f"(c[3])
        : "r"(a[0]), "r"(a[1]), "r"(a[2]), "r"(a[3]), "r"(b[0]), "r"(b[1]));
}
__device__ __forceinline__ void cp16(uint32_t saddr, const void* g) {
    asm volatile("cp.async.cg.shared.global [%0], [%1], 16;"
                 :: "r"(saddr), "l"(g) : "memory");
}
__device__ __forceinline__ float ex2(float x) {
    float r;
    asm("ex2.approx.f32 %0, %1;" : "=f"(r) : "f"(x));
    return r;
}
#define CP_COMMIT() asm volatile("cp.async.commit_group;" ::: "memory")
#define CP_WAIT(n)  asm volatile("cp.async.wait_group %0;" :: "n"(n) : "memory")

#define A_OFF  0u
#define B0_OFF 32768u
#define B1_OFF 65536u
#define SMEM_TOTAL 98304

// ---------------------------------------------------------------------------
// Kernel 1: normalize rows -> f16 tables; class sums via register-first
// reduction (warp regs -> smem atomics (8-way) -> 128 global atomics/address).
// Grid 128 x 256: warp w owns rows base + w*8 .. +7.
// ---------------------------------------------------------------------------
__global__ __launch_bounds__(256)
void prep_kernel(const float* __restrict__ zi,
                 const float* __restrict__ zj,
                 const int*   __restrict__ y, int B,
                 float* __restrict__ out) {
    __shared__ float cls_s[2][D];
    __shared__ int   cnt_s[2];
    int warp = threadIdx.x >> 5, lane = threadIdx.x & 31;
    int t = threadIdx.x;
    if (t < 2 * D) ((float*)cls_s)[t] = 0.f;
    if (t < 2) cnt_s[t] = 0;
    if (blockIdx.x == 0 && t == 0) out[0] = 0.f;

    int base = blockIdx.x * 64 + warp * 8;     // 64 rows per block
    float acc0[4] = {0.f, 0.f, 0.f, 0.f};      // class-0 partial (this lane's dims)
    float acc1[4] = {0.f, 0.f, 0.f, 0.f};      // class-1 partial
    int   c1 = 0;                              // class-1 row count (of 8)

    __syncthreads();

    #pragma unroll 2
    for (int i = 0; i < 8; i++) {
        int row = base + i;
        const float* src = (row < B) ? (zi + (size_t)row * D)
                                     : (zj + (size_t)(row - B) * D);
        float4 v = ((const float4*)src)[lane];
        float ss = v.x * v.x + v.y * v.y + v.z * v.z + v.w * v.w;
        #pragma unroll
        for (int o = 16; o > 0; o >>= 1) ss += __shfl_xor_sync(0xffffffffu, ss, o);
        float s = 1.f / fmaxf(sqrtf(ss), 1e-8f);
        float4 pn = make_float4(v.x * s, v.y * s, v.z * s, v.w * s);

        __half2 h0 = __floats2half2_rn(pn.x, pn.y);
        __half2 h1 = __floats2half2_rn(pn.z, pn.w);
        uint2 u;
        u.x = *reinterpret_cast<unsigned int*>(&h0);
        u.y = *reinterpret_cast<unsigned int*>(&h1);
        ((uint2*)(g_ph + (size_t)row * D))[lane] = u;

        __half2 a0 = __floats2half2_rn(pn.x * EX2K, pn.y * EX2K);
        __half2 a1 = __floats2half2_rn(pn.z * EX2K, pn.w * EX2K);
        uint2 ua;
        ua.x = *reinterpret_cast<unsigned int*>(&a0);
        ua.y = *reinterpret_cast<unsigned int*>(&a1);
        ((uint2*)(g_phA + (size_t)row * D))[lane] = ua;

        int lbl = y[(row < B) ? row : (row - B)];
        if (lbl) {
            acc1[0] += pn.x; acc1[1] += pn.y; acc1[2] += pn.z; acc1[3] += pn.w;
            c1++;
        } else {
            acc0[0] += pn.x; acc0[1] += pn.y; acc0[2] += pn.z; acc0[3] += pn.w;
        }
    }

    // per-warp partials -> smem (max 8-way contention per address)
    #pragma unroll
    for (int k = 0; k < 4; k++) {
        atomicAdd(&cls_s[0][lane * 4 + k], acc0[k]);
        atomicAdd(&cls_s[1][lane * 4 + k], acc1[k]);
    }
    if (lane == 0) atomicAdd(&cnt_s[1], c1);
    if (t < 64) g_S[blockIdx.x * 64 + t] = 0.f;
    __syncthreads();

    if (t < 2 * D) atomicAdd(&((float*)g_cls)[t], ((float*)cls_s)[t]);
    if (t == 0) atomicAdd(&g_cnt[1], cnt_s[1]);
    // g_cnt[0] derived in finalize as NMAX - g_cnt[1]
}

// ---------------------------------------------------------------------------
__device__ __forceinline__ void load_tile(uint32_t dst, const __half* table,
                                          int base, int tid) {
    for (int u = tid; u < TM * 16; u += 256) {
        int rr = u >> 4, cc = u & 15;
        cp16(dst + (uint32_t)rr * 256u + (uint32_t)((cc ^ (rr & 7)) << 4),
             table + (size_t)(base + rr) * D + cc * 8);
    }
}

// ---------------------------------------------------------------------------
// Kernel 2: persistent symmetric HMMA, software-pipelined K loop.
// ---------------------------------------------------------------------------
__global__ __launch_bounds__(256, 2)
void main_kernel() {
    extern __shared__ char sm[];
    const uint32_t smb = smem_u32(sm);

    const int tid = threadIdx.x, lane = tid & 31, wid = tid >> 5;
    const int warp_m = wid >> 2, warp_n = wid & 3;

    const int lo = (int)(((long long)blockIdx.x * NTILES_TRI) / GMAIN);
    const int hi = (int)(((long long)(blockIdx.x + 1) * NTILES_TRI) / GMAIN);

    int r = 0;
    while ((r + 1) * (2 * NTT - r) / 2 <= lo) r++;
    int c = r + (lo - r * (2 * NTT - r + 1) / 2);

    load_tile(smb + A_OFF, g_phA, r * TM, tid);
    load_tile(smb + B0_OFF, g_ph, c * TM, tid);
    CP_COMMIT();

    const int g = lane >> 3;
    uint32_t a_off[4], a_msk[4];
    #pragma unroll
    for (int mt = 0; mt < 4; mt++) {
        int row = warp_m * 64 + mt * 16 + (g & 1) * 8 + (lane & 7);
        a_off[mt] = smb + A_OFF + (uint32_t)row * 256u;
        a_msk[mt] = (uint32_t)(row & 7);
    }
    const int a_cadd = g >> 1;
    uint32_t b_row[2], b_msk[2];
    #pragma unroll
    for (int nt2 = 0; nt2 < 2; nt2++) {
        int row = warp_n * 32 + nt2 * 16 + (g >> 1) * 8 + (lane & 7);
        b_row[nt2] = (uint32_t)row * 256u;
        b_msk[nt2] = (uint32_t)(row & 7);
    }
    const int b_cadd = g & 1;

#define AADDR(mt, ks) (a_off[mt] + (uint32_t)(((2 * (ks) + a_cadd) ^ a_msk[mt]) << 4))
#define BADDR(n2, ks) (bbase + b_row[n2] + (uint32_t)(((2 * (ks) + b_cadd) ^ b_msk[n2]) << 4))

    float es[8];
    #pragma unroll
    for (int s = 0; s < 8; s++) es[s] = 0.f;
    int parity = 0;
    int accr = r;

    for (int t = lo; t < hi; t++) {
        const int tr = r, tc = c;
        const bool isdiag = (tr == tc);
        int nr = r, nc = c + 1;
        if (nc == NTT) { nr = r + 1; nc = nr; }
        const bool havenext = (t + 1 < hi);

        __syncthreads();
        if (havenext) {
            load_tile(smb + (parity ? B0_OFF : B1_OFF), g_ph, nc * TM, tid);
            CP_COMMIT();
            CP_WAIT(1);
        } else {
            CP_WAIT(0);
        }
        __syncthreads();

        const uint32_t bbase = smb + (parity ? B1_OFF : B0_OFF);
        float acc[4][4][4];
        #pragma unroll
        for (int mt = 0; mt < 4; mt++)
            #pragma unroll
            for (int nt = 0; nt < 4; nt++)
                #pragma unroll
                for (int k = 0; k < 4; k++) acc[mt][nt][k] = 0.f;

        uint32_t afb[2][4], bfb[2][2][4];
        ldsm4(bfb[0][0], BADDR(0, 0));
        ldsm4(bfb[0][1], BADDR(1, 0));
        ldsm4(afb[0], AADDR(0, 0));
        #pragma unroll
        for (int ks = 0; ks < 8; ks++) {
            const int kb = ks & 1;
            if (ks < 7) {
                ldsm4(bfb[kb ^ 1][0], BADDR(0, ks + 1));
                ldsm4(bfb[kb ^ 1][1], BADDR(1, ks + 1));
            }
            #pragma unroll
            for (int mt = 0; mt < 4; mt++) {
                const int ab = mt & 1;
                if (mt < 3)      ldsm4(afb[ab ^ 1], AADDR(mt + 1, ks));
                else if (ks < 7) ldsm4(afb[ab ^ 1], AADDR(0, ks + 1));
                #pragma unroll
                for (int nt = 0; nt < 4; nt++)
                    mma16816(acc[mt][nt], afb[ab], &bfb[kb][nt >> 1][(nt & 1) * 2]);
            }
        }

        float csl[8];
        #pragma unroll
        for (int s = 0; s < 8; s++) csl[s] = 0.f;
        #pragma unroll
        for (int nt = 0; nt < 4; nt++) {
            #pragma unroll
            for (int mt = 0; mt < 4; mt++) {
                #pragma unroll
                for (int q = 0; q < 4; q++) {
                    float e = ex2(acc[mt][nt][q]);
                    if (isdiag) {
                        int jl = warp_n * 32 + nt * 8 + (lane & 3) * 2 + (q & 1);
                        int il = warp_m * 64 + mt * 16 + (lane >> 2) + ((q < 2) ? 0 : 8);
                        if (jl == il) e = 0.f;
                    }
                    es[mt * 2 + (q >> 1)] += e;
                    csl[nt * 2 + (q & 1)] += e;
                }
            }
        }
        if (!isdiag) {
            int colBase = tc * TM;
            #pragma unroll
            for (int s = 0; s < 8; s++) {
                float v = csl[s];
                v += __shfl_xor_sync(0xffffffffu, v, 4);
                v += __shfl_xor_sync(0xffffffffu, v, 8);
                v += __shfl_xor_sync(0xffffffffu, v, 16);
                if (lane < 4)
                    atomicAdd(&g_S[colBase + warp_n * 32 + (s >> 1) * 8 + lane * 2 + (s & 1)], v);
            }
        }

        if (havenext && nr != tr) {
            int rowBase = accr * TM;
            #pragma unroll
            for (int s = 0; s < 8; s++) {
                float e = es[s];
                e += __shfl_xor_sync(0xffffffffu, e, 1);
                e += __shfl_xor_sync(0xffffffffu, e, 2);
                if ((lane & 3) == 0)
                    atomicAdd(&g_S[rowBase + warp_m * 64 + (s >> 1) * 16 +
                                   (lane >> 2) + (s & 1) * 8], e);
                es[s] = 0.f;
            }
            accr = nr;
            __syncthreads();
            load_tile(smb + A_OFF, g_phA, nr * TM, tid);
            CP_COMMIT();
        }
        r = nr; c = nc; parity ^= 1;
    }

    {
        int rowBase = accr * TM;
        #pragma unroll
        for (int s = 0; s < 8; s++) {
            float e = es[s];
            e += __shfl_xor_sync(0xffffffffu, e, 1);
            e += __shfl_xor_sync(0xffffffffu, e, 2);
            if ((lane & 3) == 0)
                atomicAdd(&g_S[rowBase + warp_m * 64 + (s >> 1) * 16 +
                               (lane >> 2) + (s & 1) * 8], e);
        }
    }
#undef AADDR
#undef BADDR
}

// ---------------------------------------------------------------------------
// Kernel 3: loss = sum_i log S_i - tau_inv * sum_c (||S_c||^2 - cnt_c)/(cnt_c-1)
// Block 0 restores g_cls/g_cnt to zero for the next graph replay.
// ---------------------------------------------------------------------------
__global__ void finalize_kernel(float* __restrict__ out) {
    __shared__ float ws[8];
    int t = threadIdx.x, lane = t & 31, warp = t >> 5;
    int row = blockIdx.x * 256 + t;
    float local = logf(g_S[row]);
    #pragma unroll
    for (int o = 16; o > 0; o >>= 1) local += __shfl_xor_sync(0xffffffffu, local, o);
    if (lane == 0) ws[warp] = local;
    __syncthreads();
    if (t < 8) {
        float v = ws[t];
        #pragma unroll
        for (int o = 4; o > 0; o >>= 1) v += __shfl_xor_sync(0x000000ffu, v, o);
        if (t == 0) atomicAdd(out, v);
    }
    if (blockIdx.x == 0) {
        if (warp < 2) {
            float4 cv = ((const float4*)(g_cls[warp]))[lane];
            float nsq = cv.x * cv.x + cv.y * cv.y + cv.z * cv.z + cv.w * cv.w;
            #pragma unroll
            for (int o = 16; o > 0; o >>= 1) nsq += __shfl_xor_sync(0xffffffffu, nsq, o);
            if (lane == 0) {
                float cnt = (warp == 1) ? (float)g_cnt[1]
                                        : (float)(NMAX - g_cnt[1]);
                atomicAdd(out, -TAU_INV * (nsq - cnt) / (cnt - 1.f));
            }
        }
        __syncthreads();
        if (t < 2 * D) ((float*)g_cls)[t] = 0.f;
        if (t < 2) g_cnt[t] = 0;
    }
}

// ---------------------------------------------------------------------------
extern "C" void kernel_launch(void* const* d_in, const int* in_sizes, int n_in,
                              void* d_out, int out_size) {
    const float* zi = (const float*)d_in[0];
    const float* zj = (const float*)d_in[1];
    const int*   y  = (const int*)d_in[2];
    int B = in_sizes[2];
    int N = 2 * B;

    prep_kernel<<<N / 64, 256>>>(zi, zj, y, B, (float*)d_out);

    cudaFuncSetAttribute(main_kernel, cudaFuncAttributeMaxDynamicSharedMemorySize,
                         SMEM_TOTAL);
    main_kernel<<<GMAIN, 256, SMEM_TOTAL>>>();

    finalize_kernel<<<N / 256, 256>>>((float*)d_out);
}